// round 1
// baseline (speedup 1.0000x reference)
#include <cuda_runtime.h>

// ---------------------------------------------------------------------------
// MultiHeadAttention with Shaw-style relative position embeddings.
// Fixed shapes per reference: B=2, L=2048, E=1024, H=16, hd=64, clip=16.
//
// Pipeline:
//   1) qh = relu(q @ Wq^T + bq)  -> split-head layout [BH][L][64]   (gemm_relu, split=1)
//      kh, vh likewise
//   2) qrel[bh][q][d33] = qh[bh][q][:] . rel_k[d33][:]              (qrel_kernel)
//   3) flash-style attention per (bh, 64-query tile):
//        S = Qs Ks^T + qrel[dist]  (scaled 1/32), online softmax,
//        O += P V, plus 33 relative-value weights per query row
//        (d=0: sum_{k<=q-16} p, d=32: sum_{k>=q+16} p, interior: single p)
//      -> ctx merged-head layout [B*L][1024]                        (attn_kernel)
//   4) out = relu(ctx @ Wo^T + bo)                                  (gemm_relu, split=0)
// ---------------------------------------------------------------------------

#define BATCH  2
#define SEQ    2048
#define EMB    1024
#define NHEADS 16
#define HDIM   64
#define DKEY   1024
#define CLIPV  16
#define ND     33            // 2*CLIP+1
#define MROWS  (BATCH*SEQ)   // 4096
#define BH     (BATCH*NHEADS)// 32

// Scratch (device globals: no allocation allowed)
__device__ float g_qh[BH*SEQ*HDIM];
__device__ float g_kh[BH*SEQ*HDIM];
__device__ float g_vh[BH*SEQ*HDIM];
__device__ float g_qrel[BH*SEQ*ND];
__device__ float g_ctx[MROWS*DKEY];

// ---------------------------------------------------------------------------
// Fused GEMM + bias + ReLU:  out = relu(X @ W^T + bias)
// X: (MROWS, EMB) row-major; W: (N=1024, EMB) row-major; N fixed at 1024.
// split=1 -> write into split-head layout [b][h][l][d]; split=0 -> row-major.
// Tile: 64x64, BK=16, 256 threads, 4x4 microtile per thread.
// ---------------------------------------------------------------------------
__global__ void __launch_bounds__(256) gemm_relu(
    const float* __restrict__ X, const float* __restrict__ W,
    const float* __restrict__ bias, float* __restrict__ out, int split)
{
    __shared__ float Xs[64][17];
    __shared__ float Ws[64][17];

    const int tid = threadIdx.x;
    const int tx = tid & 15;          // 0..15 (n microtile)
    const int ty = tid >> 4;          // 0..15 (m microtile)
    const int m0 = blockIdx.y * 64;
    const int n0 = blockIdx.x * 64;

    const int lr = tid >> 2;          // 0..63 load row
    const int lc = (tid & 3) * 4;     // 0,4,8,12 load col

    float acc[4][4];
    #pragma unroll
    for (int i = 0; i < 4; i++)
        #pragma unroll
        for (int j = 0; j < 4; j++) acc[i][j] = 0.f;

    const float* Xrow = X + (size_t)(m0 + lr) * EMB + lc;
    const float* Wrow = W + (size_t)(n0 + lr) * EMB + lc;

    for (int kt = 0; kt < EMB; kt += 16) {
        float4 xa = *reinterpret_cast<const float4*>(Xrow + kt);
        float4 wa = *reinterpret_cast<const float4*>(Wrow + kt);
        Xs[lr][lc+0] = xa.x; Xs[lr][lc+1] = xa.y; Xs[lr][lc+2] = xa.z; Xs[lr][lc+3] = xa.w;
        Ws[lr][lc+0] = wa.x; Ws[lr][lc+1] = wa.y; Ws[lr][lc+2] = wa.z; Ws[lr][lc+3] = wa.w;
        __syncthreads();
        #pragma unroll
        for (int kk = 0; kk < 16; kk++) {
            float a[4], b[4];
            #pragma unroll
            for (int i = 0; i < 4; i++) a[i] = Xs[ty*4+i][kk];
            #pragma unroll
            for (int j = 0; j < 4; j++) b[j] = Ws[tx*4+j][kk];
            #pragma unroll
            for (int i = 0; i < 4; i++)
                #pragma unroll
                for (int j = 0; j < 4; j++)
                    acc[i][j] = fmaf(a[i], b[j], acc[i][j]);
        }
        __syncthreads();
    }

    #pragma unroll
    for (int i = 0; i < 4; i++) {
        int m = m0 + ty*4 + i;
        int bidx = m >> 11;       // / SEQ
        int l    = m & (SEQ-1);
        #pragma unroll
        for (int j = 0; j < 4; j++) {
            int n = n0 + tx*4 + j;
            float v = acc[i][j] + bias[n];
            v = v > 0.f ? v : 0.f;
            if (split) {
                int h = n >> 6, d = n & 63;
                out[(((size_t)(bidx*NHEADS + h))*SEQ + l)*HDIM + d] = v;
            } else {
                out[(size_t)m*DKEY + n] = v;
            }
        }
    }
}

// ---------------------------------------------------------------------------
// qrel[bh][q][d] = qh[bh][q][:] . rel_k[d][:]
// ---------------------------------------------------------------------------
__global__ void __launch_bounds__(256) qrel_kernel(const float* __restrict__ rel_k)
{
    __shared__ float Qs[64*HDIM];
    __shared__ float Rk[ND*HDIM];
    const int bh = blockIdx.y;
    const int q0 = blockIdx.x * 64;

    const float* qbase = &g_qh[((size_t)bh*SEQ + q0)*HDIM];
    for (int i = threadIdx.x; i < 64*HDIM; i += 256) Qs[i] = qbase[i];
    for (int i = threadIdx.x; i < ND*HDIM; i += 256) Rk[i] = rel_k[i];
    __syncthreads();

    for (int i = threadIdx.x; i < 64*ND; i += 256) {
        int q = i / ND, d = i - q*ND;
        float s = 0.f;
        #pragma unroll 8
        for (int c = 0; c < HDIM; c++) s = fmaf(Qs[q*HDIM+c], Rk[d*HDIM+c], s);
        g_qrel[((size_t)bh*SEQ + q0 + q)*ND + d] = s;
    }
}

// ---------------------------------------------------------------------------
// Flash-style attention. One block = one (bh, 64-query tile).
// 256 threads: thread t owns query row q=t/4, column segment seg=t%4 (16 wide).
// Dynamic smem layout (floats, rows padded to 65 for bank spread):
//   Qs[64*65] Ks[64*65] Vs[64*65] Ps[64*65] QR[64*33] RB[64*31] RV[33*64]
// ---------------------------------------------------------------------------
#define SM_QS 0
#define SM_KS 4160
#define SM_VS 8320
#define SM_PS 12480
#define SM_QR 16640
#define SM_RB 18752
#define SM_RV 20736
#define SM_TOTAL_FLOATS 22848   // 91392 bytes

__global__ void __launch_bounds__(256) attn_kernel(const float* __restrict__ rel_v)
{
    extern __shared__ float sm[];
    float* Qs = sm + SM_QS;
    float* Ks = sm + SM_KS;
    float* Vs = sm + SM_VS;
    float* Ps = sm + SM_PS;
    float* QR = sm + SM_QR;
    float* RB = sm + SM_RB;
    float* RV = sm + SM_RV;

    const int bh  = blockIdx.y;
    const int q0  = blockIdx.x * 64;
    const int tid = threadIdx.x;
    const int q   = tid >> 2;        // query row within tile
    const int seg = tid & 3;         // 16-wide column segment
    const int col = seg * 16;
    const float inv_scale = 0.03125f;   // 1/sqrt(1024)

    // Prologue loads
    const float* qbase = &g_qh[((size_t)bh*SEQ + q0)*HDIM];
    for (int i = tid; i < 64*HDIM; i += 256) {
        int r = i >> 6, c = i & 63;
        Qs[r*65 + c] = qbase[i];
    }
    const float* qrbase = &g_qrel[((size_t)bh*SEQ + q0)*ND];
    for (int i = tid; i < 64*ND; i += 256) QR[i] = qrbase[i];
    for (int i = tid; i < ND*HDIM; i += 256) RV[i] = rel_v[i];
    for (int i = tid; i < 64*31; i += 256) RB[i] = 0.f;
    __syncthreads();

    float O[16];
    #pragma unroll
    for (int j = 0; j < 16; j++) O[j] = 0.f;
    float m = -1e30f, l = 0.f, sum_lo = 0.f, sum_hi = 0.f;

    const int qg = q0 + q;

    for (int kt = 0; kt < SEQ/64; kt++) {
        // Load K,V tiles (coalesced, padded store)
        const float* kbase = &g_kh[((size_t)bh*SEQ + kt*64)*HDIM];
        const float* vbase = &g_vh[((size_t)bh*SEQ + kt*64)*HDIM];
        for (int i = tid; i < 64*HDIM; i += 256) {
            int r = i >> 6, c = i & 63;
            Ks[r*65 + c] = kbase[i];
            Vs[r*65 + c] = vbase[i];
        }
        __syncthreads();

        // S = Q K^T for this thread's 16 columns
        float s[16];
        #pragma unroll
        for (int j = 0; j < 16; j++) s[j] = 0.f;
        #pragma unroll 4
        for (int d = 0; d < HDIM; d++) {
            float qv = Qs[q*65 + d];
            #pragma unroll
            for (int j = 0; j < 16; j++)
                s[j] = fmaf(qv, Ks[(col + j)*65 + d], s[j]);
        }

        // + relative-key term, scale, tile row-max
        const int kg0 = kt*64 + col;
        float tmax = -1e30f;
        #pragma unroll
        for (int j = 0; j < 16; j++) {
            int diff = kg0 + j - qg;
            int dcl = diff < -CLIPV ? 0 : (diff > CLIPV ? 2*CLIPV : diff + CLIPV);
            s[j] = (s[j] + QR[q*ND + dcl]) * inv_scale;
            tmax = fmaxf(tmax, s[j]);
        }
        tmax = fmaxf(tmax, __shfl_xor_sync(0xffffffffu, tmax, 1));
        tmax = fmaxf(tmax, __shfl_xor_sync(0xffffffffu, tmax, 2));

        float mnew = fmaxf(m, tmax);
        float corr = __expf(m - mnew);
        m = mnew;
        l *= corr; sum_lo *= corr; sum_hi *= corr;
        #pragma unroll
        for (int j = 0; j < 16; j++) O[j] *= corr;
        // Rescale interior rel-weight buffer for row q (4 lanes cooperate)
        for (int dd = seg; dd < 31; dd += 4) RB[q*31 + dd] *= corr;
        __syncwarp();

        // exp, accumulate denominator + rel classes, stage P
        #pragma unroll
        for (int j = 0; j < 16; j++) {
            float p = __expf(s[j] - mnew);
            l += p;
            int diff = kg0 + j - qg;
            if (diff <= -CLIPV)      sum_lo += p;
            else if (diff >= CLIPV)  sum_hi += p;
            else                     RB[q*31 + (diff + CLIPV - 1)] = p;
            Ps[q*65 + col + j] = p;
        }
        __syncwarp();

        // O += P V  (thread's 16 output dims)
        #pragma unroll 4
        for (int k = 0; k < 64; k++) {
            float pv = Ps[q*65 + k];
            #pragma unroll
            for (int j = 0; j < 16; j++)
                O[j] = fmaf(pv, Vs[k*65 + col + j], O[j]);
        }
        __syncthreads();   // protect Ks/Vs before next tile's load
    }

    // Reduce denominator and boundary sums across the 4 lanes of the row
    l      += __shfl_xor_sync(0xffffffffu, l, 1);
    l      += __shfl_xor_sync(0xffffffffu, l, 2);
    sum_lo += __shfl_xor_sync(0xffffffffu, sum_lo, 1);
    sum_lo += __shfl_xor_sync(0xffffffffu, sum_lo, 2);
    sum_hi += __shfl_xor_sync(0xffffffffu, sum_hi, 1);
    sum_hi += __shfl_xor_sync(0xffffffffu, sum_hi, 2);
    __syncwarp();

    // Relative-value contributions: O += sum_d w(d) * rel_v[d]
    #pragma unroll
    for (int j = 0; j < 16; j++)
        O[j] = fmaf(sum_lo, RV[0*HDIM + col + j], O[j]);
    #pragma unroll
    for (int j = 0; j < 16; j++)
        O[j] = fmaf(sum_hi, RV[32*HDIM + col + j], O[j]);
    for (int dd = 1; dd < 32; dd++) {
        float w = RB[q*31 + dd - 1];
        #pragma unroll
        for (int j = 0; j < 16; j++)
            O[j] = fmaf(w, RV[dd*HDIM + col + j], O[j]);
    }

    const float invl = 1.0f / l;
    const int bidx = bh / NHEADS, h = bh % NHEADS;
    float* dst = &g_ctx[((size_t)(bidx*SEQ + qg))*DKEY + h*HDIM + col];
    #pragma unroll
    for (int j = 0; j < 16; j++) dst[j] = O[j] * invl;
}

// ---------------------------------------------------------------------------
// Launch
// ---------------------------------------------------------------------------
extern "C" void kernel_launch(void* const* d_in, const int* in_sizes, int n_in,
                              void* d_out, int out_size)
{
    (void)in_sizes; (void)n_in; (void)out_size;
    const float* q    = (const float*)d_in[0];
    const float* k    = (const float*)d_in[1];
    const float* v    = (const float*)d_in[2];
    const float* Wq   = (const float*)d_in[3];
    const float* bq   = (const float*)d_in[4];
    const float* Wk   = (const float*)d_in[5];
    const float* bk   = (const float*)d_in[6];
    const float* Wv   = (const float*)d_in[7];
    const float* bv   = (const float*)d_in[8];
    const float* Wo   = (const float*)d_in[9];
    const float* bo   = (const float*)d_in[10];
    const float* relk = (const float*)d_in[11];
    const float* relv = (const float*)d_in[12];
    float* out = (float*)d_out;

    float *qh, *kh, *vh, *ctx;
    cudaGetSymbolAddress((void**)&qh, g_qh);
    cudaGetSymbolAddress((void**)&kh, g_kh);
    cudaGetSymbolAddress((void**)&vh, g_vh);
    cudaGetSymbolAddress((void**)&ctx, g_ctx);

    cudaFuncSetAttribute(attn_kernel, cudaFuncAttributeMaxDynamicSharedMemorySize,
                         SM_TOTAL_FLOATS * 4);

    dim3 gGemm(DKEY/64, MROWS/64);   // (16, 64)
    gemm_relu<<<gGemm, 256>>>(q, Wq, bq, qh, 1);
    gemm_relu<<<gGemm, 256>>>(k, Wk, bk, kh, 1);
    gemm_relu<<<gGemm, 256>>>(v, Wv, bv, vh, 1);

    dim3 gAttn(SEQ/64, BH);          // (32, 32)
    qrel_kernel<<<gAttn, 256>>>(relk);
    attn_kernel<<<gAttn, 256, SM_TOTAL_FLOATS * 4>>>(relv);

    gemm_relu<<<gGemm, 256>>>(ctx, Wo, bo, out, 0);
}

// round 7
// speedup vs baseline: 3.4939x; 3.4939x over previous
#include <cuda_runtime.h>
#include <cstdint>

// ---------------------------------------------------------------------------
// MultiHeadAttention w/ Shaw relative position. B=2, L=2048, E=1024, H=16,
// hd=64, clip=16.
// NOTE: harness compiles via compute_103 (no 'a') -> tcgen05 unavailable.
// Tensor cores reached via mma.sync.m16n8k8 tf32 (sm_80+ path).
//  1) q/k/v projections + ReLU: mma.sync tf32 GEMM -> split-head [BH][L][64]
//  2) qrel[bh][q][d33] = qh . rel_k[d33]   (bank-conflict-free)
//  3) flash attention, 64x64 tiles, 4x4 register microtiles, LDS.128 only
//  4) out projection + ReLU: mma.sync tf32 GEMM
// ---------------------------------------------------------------------------

#define BATCH  2
#define SEQ    2048
#define EMB    1024
#define NHEADS 16
#define HDIM   64
#define DKEY   1024
#define CLIPV  16
#define ND     33
#define MROWS  (BATCH*SEQ)
#define BH     (BATCH*NHEADS)

__device__ __align__(256) float g_qh[BH*SEQ*HDIM];
__device__ __align__(256) float g_kh[BH*SEQ*HDIM];
__device__ __align__(256) float g_vh[BH*SEQ*HDIM];
__device__ __align__(256) float g_qrel[BH*SEQ*ND];
__device__ __align__(256) float g_ctx[MROWS*DKEY];

__device__ __forceinline__ float tf32r(float x) {
    asm("cvt.rna.tf32.f32 %0, %0;" : "+f"(x));
    return x;
}
__device__ __forceinline__ void mma_tf32(
    float& d0, float& d1, float& d2, float& d3,
    uint32_t a0, uint32_t a1, uint32_t a2, uint32_t a3,
    uint32_t b0, uint32_t b1)
{
    asm volatile(
        "mma.sync.aligned.m16n8k8.row.col.f32.tf32.tf32.f32 "
        "{%0,%1,%2,%3}, {%4,%5,%6,%7}, {%8,%9}, {%0,%1,%2,%3};"
        : "+f"(d0), "+f"(d1), "+f"(d2), "+f"(d3)
        : "r"(a0), "r"(a1), "r"(a2), "r"(a3), "r"(b0), "r"(b1));
}

// ---------------------------------------------------------------------------
// mma.sync tf32 GEMM: out = relu(X @ W^T + bias).  X:(4096,1024), W:(1024,1024)
// CTA 128x128, BK=16, double-buffered smem (stride 20 -> conflict-free frags).
// 8 warps as 4(m) x 2(n): warp tile 32x64 = 2 mtiles x 8 ntiles of m16n8k8.
// ---------------------------------------------------------------------------
#define PM_PAD 20
#define PM_BUF (128 * PM_PAD)                 // floats per buffer
#define PSMEM  (4 * PM_BUF * 4)               // 2 bufs x (A,B) = 40960 bytes

__global__ void __launch_bounds__(256) proj_mma(
    const float* __restrict__ X, const float* __restrict__ W,
    const float* __restrict__ bias, float* __restrict__ out, int split)
{
    extern __shared__ float smf[];
    float* As = smf;                 // [2][128][PM_PAD]
    float* Bs = smf + 2 * PM_BUF;    // [2][128][PM_PAD]

    const int tid = threadIdx.x;
    const int lane = tid & 31, wid = tid >> 5;
    const int wm = wid & 3, wn = wid >> 2;
    const int lr = lane >> 2, lq = lane & 3;
    const int m0 = blockIdx.y * 128, n0 = blockIdx.x * 128;

    const float4* X4 = (const float4*)X;
    const float4* W4 = (const float4*)W;

    // chunk loader indices: 512 float4 per matrix per chunk; 2 per thread
    const int r0 = tid >> 2, c0 = tid & 3;          // idx = tid
    const int r1 = (tid + 256) >> 2, c1 = tid & 3;  // idx = tid+256 (c same)

    float c[2][8][4];
    #pragma unroll
    for (int i = 0; i < 2; i++)
        #pragma unroll
        for (int j = 0; j < 8; j++)
            #pragma unroll
            for (int t = 0; t < 4; t++) c[i][j][t] = 0.f;

    // load chunk 0 into buffer 0
    {
        float4 xa0 = X4[(size_t)(m0 + r0) * 256 + c0];
        float4 xa1 = X4[(size_t)(m0 + r1) * 256 + c1];
        float4 wb0 = W4[(size_t)(n0 + r0) * 256 + c0];
        float4 wb1 = W4[(size_t)(n0 + r1) * 256 + c1];
        float* a = As; float* b = Bs;
        a[r0*PM_PAD + c0*4+0] = tf32r(xa0.x); a[r0*PM_PAD + c0*4+1] = tf32r(xa0.y);
        a[r0*PM_PAD + c0*4+2] = tf32r(xa0.z); a[r0*PM_PAD + c0*4+3] = tf32r(xa0.w);
        a[r1*PM_PAD + c1*4+0] = tf32r(xa1.x); a[r1*PM_PAD + c1*4+1] = tf32r(xa1.y);
        a[r1*PM_PAD + c1*4+2] = tf32r(xa1.z); a[r1*PM_PAD + c1*4+3] = tf32r(xa1.w);
        b[r0*PM_PAD + c0*4+0] = tf32r(wb0.x); b[r0*PM_PAD + c0*4+1] = tf32r(wb0.y);
        b[r0*PM_PAD + c0*4+2] = tf32r(wb0.z); b[r0*PM_PAD + c0*4+3] = tf32r(wb0.w);
        b[r1*PM_PAD + c1*4+0] = tf32r(wb1.x); b[r1*PM_PAD + c1*4+1] = tf32r(wb1.y);
        b[r1*PM_PAD + c1*4+2] = tf32r(wb1.z); b[r1*PM_PAD + c1*4+3] = tf32r(wb1.w);
    }
    __syncthreads();

    for (int kc = 0; kc < 64; kc++) {
        const int buf = kc & 1;
        float4 xa0, xa1, wb0, wb1;
        if (kc + 1 < 64) {
            const int kb = (kc + 1) * 4;
            xa0 = X4[(size_t)(m0 + r0) * 256 + kb + c0];
            xa1 = X4[(size_t)(m0 + r1) * 256 + kb + c1];
            wb0 = W4[(size_t)(n0 + r0) * 256 + kb + c0];
            wb1 = W4[(size_t)(n0 + r1) * 256 + kb + c1];
        }

        const float* a = As + buf * PM_BUF;
        const float* b = Bs + buf * PM_BUF;
        #pragma unroll
        for (int ks = 0; ks < 2; ks++) {
            const int k0 = ks * 8 + lq;
            uint32_t af[2][4];
            #pragma unroll
            for (int mt = 0; mt < 2; mt++) {
                const int row = wm * 32 + mt * 16 + lr;
                af[mt][0] = __float_as_uint(a[row * PM_PAD + k0]);
                af[mt][1] = __float_as_uint(a[(row + 8) * PM_PAD + k0]);
                af[mt][2] = __float_as_uint(a[row * PM_PAD + k0 + 4]);
                af[mt][3] = __float_as_uint(a[(row + 8) * PM_PAD + k0 + 4]);
            }
            #pragma unroll
            for (int nt = 0; nt < 8; nt++) {
                const int col = wn * 64 + nt * 8 + lr;
                uint32_t b0 = __float_as_uint(b[col * PM_PAD + k0]);
                uint32_t b1 = __float_as_uint(b[col * PM_PAD + k0 + 4]);
                #pragma unroll
                for (int mt = 0; mt < 2; mt++)
                    mma_tf32(c[mt][nt][0], c[mt][nt][1], c[mt][nt][2], c[mt][nt][3],
                             af[mt][0], af[mt][1], af[mt][2], af[mt][3], b0, b1);
            }
        }

        if (kc + 1 < 64) {
            float* an = As + (buf ^ 1) * PM_BUF;
            float* bn = Bs + (buf ^ 1) * PM_BUF;
            an[r0*PM_PAD + c0*4+0] = tf32r(xa0.x); an[r0*PM_PAD + c0*4+1] = tf32r(xa0.y);
            an[r0*PM_PAD + c0*4+2] = tf32r(xa0.z); an[r0*PM_PAD + c0*4+3] = tf32r(xa0.w);
            an[r1*PM_PAD + c1*4+0] = tf32r(xa1.x); an[r1*PM_PAD + c1*4+1] = tf32r(xa1.y);
            an[r1*PM_PAD + c1*4+2] = tf32r(xa1.z); an[r1*PM_PAD + c1*4+3] = tf32r(xa1.w);
            bn[r0*PM_PAD + c0*4+0] = tf32r(wb0.x); bn[r0*PM_PAD + c0*4+1] = tf32r(wb0.y);
            bn[r0*PM_PAD + c0*4+2] = tf32r(wb0.z); bn[r0*PM_PAD + c0*4+3] = tf32r(wb0.w);
            bn[r1*PM_PAD + c1*4+0] = tf32r(wb1.x); bn[r1*PM_PAD + c1*4+1] = tf32r(wb1.y);
            bn[r1*PM_PAD + c1*4+2] = tf32r(wb1.z); bn[r1*PM_PAD + c1*4+3] = tf32r(wb1.w);
        }
        __syncthreads();
    }

    // Epilogue: bias + relu, optional split-head store
    #pragma unroll
    for (int mt = 0; mt < 2; mt++) {
        #pragma unroll
        for (int nt = 0; nt < 8; nt++) {
            const int row = m0 + wm * 32 + mt * 16 + lr;
            const int col = n0 + wn * 64 + nt * 8 + 2 * lq;
            const float bia0 = bias[col], bia1 = bias[col + 1];
            #pragma unroll
            for (int half = 0; half < 2; half++) {
                const int m = row + half * 8;
                float v0 = fmaxf(c[mt][nt][half * 2 + 0] + bia0, 0.f);
                float v1 = fmaxf(c[mt][nt][half * 2 + 1] + bia1, 0.f);
                if (split) {
                    const int bb = m >> 11, ll = m & (SEQ - 1);
                    const int h = col >> 6, d = col & 63;
                    out[(((size_t)(bb * NHEADS + h)) * SEQ + ll) * HDIM + d]     = v0;
                    out[(((size_t)(bb * NHEADS + h)) * SEQ + ll) * HDIM + d + 1] = v1;
                } else {
                    float2 v = make_float2(v0, v1);
                    *(float2*)&out[(size_t)m * DKEY + col] = v;
                }
            }
        }
    }
}

// ---------------------------------------------------------------------------
// qrel[bh][q][d] = qh[bh][q][:] . rel_k[d][:]  -- Rk padded to 65 (no conflicts)
// ---------------------------------------------------------------------------
__global__ void __launch_bounds__(256) qrel_kernel(const float* __restrict__ rel_k)
{
    __shared__ float Qs[64 * 64];
    __shared__ float Rk[ND * 65];
    const int bh = blockIdx.y, q0 = blockIdx.x * 64;

    const float* qb = g_qh + ((size_t)bh * SEQ + q0) * HDIM;
    for (int i = threadIdx.x; i < 64 * 64; i += 256) Qs[i] = qb[i];
    for (int i = threadIdx.x; i < ND * 64; i += 256) {
        int d = i >> 6, cc = i & 63;
        Rk[d * 65 + cc] = rel_k[i];
    }
    __syncthreads();

    for (int i = threadIdx.x; i < 64 * ND; i += 256) {
        int q = i / ND, d = i - q * ND;
        float s = 0.f;
        #pragma unroll 8
        for (int cc = 0; cc < 64; cc++) s = fmaf(Qs[q * 64 + cc], Rk[d * 65 + cc], s);
        g_qrel[((size_t)bh * SEQ + q0 + q) * ND + d] = s;
    }
}

// ---------------------------------------------------------------------------
// Flash attention, 64q x 64k tiles. 256 threads: ty=tid/16 owns q rows
// ty*4..+3, tx=tid%16 owns k cols (and output dims) tx*4..+3.
// All inner-loop smem traffic is conflict-free LDS.128 on transposed tiles.
// ---------------------------------------------------------------------------
#define APAD 68
#define A_QST 0
#define A_KST (A_QST + 64*APAD)
#define A_VS  (A_KST + 64*APAD)
#define A_PST (A_VS  + 64*APAD)
#define A_QR  (A_PST + 64*APAD)
#define A_RB  (A_QR + 64*ND)
#define A_RV  (A_RB + 64*32)
#define A_TOT (A_RV + ND*64)     // 23680 floats = 94720 B

__global__ void __launch_bounds__(256) attn_kernel(const float* __restrict__ rel_v)
{
    extern __shared__ float smf[];
    float* Qst = smf + A_QST;
    float* Kst = smf + A_KST;
    float* Vs  = smf + A_VS;
    float* Pst = smf + A_PST;
    float* QR  = smf + A_QR;
    float* RB  = smf + A_RB;
    float* RV  = smf + A_RV;

    const int tid = threadIdx.x;
    const int ty = tid >> 4, tx = tid & 15;
    const int bh = blockIdx.y, q0 = blockIdx.x * 64;

    // Prologue: Q transposed, QR, RV, RB=0
    const float4* q4 = (const float4*)(g_qh + ((size_t)bh * SEQ + q0) * HDIM);
    for (int i = tid; i < 1024; i += 256) {
        int r = i >> 4, d = (i & 15) << 2;
        float4 v = q4[i];
        Qst[(d + 0) * APAD + r] = v.x;
        Qst[(d + 1) * APAD + r] = v.y;
        Qst[(d + 2) * APAD + r] = v.z;
        Qst[(d + 3) * APAD + r] = v.w;
    }
    const float* qr = g_qrel + ((size_t)bh * SEQ + q0) * ND;
    for (int i = tid; i < 64 * ND; i += 256) QR[i] = qr[i];
    const float4* rv4 = (const float4*)rel_v;
    for (int i = tid; i < (ND * 64) / 4; i += 256) ((float4*)RV)[i] = rv4[i];
    for (int i = tid; i < 64 * 32; i += 256) RB[i] = 0.f;
    __syncthreads();

    float O[4][4] = {};
    float m[4], l[4] = {}, lo[4] = {}, hi[4] = {};
    #pragma unroll
    for (int i = 0; i < 4; i++) m[i] = -1e30f;
    const int qg0 = q0 + ty * 4;

    for (int kt = 0; kt < SEQ / 64; kt++) {
        const float4* k4 = (const float4*)(g_kh + ((size_t)bh * SEQ + kt * 64) * HDIM);
        const float4* v4 = (const float4*)(g_vh + ((size_t)bh * SEQ + kt * 64) * HDIM);
        for (int i = tid; i < 1024; i += 256) {
            int r = i >> 4, d = (i & 15) << 2;
            float4 kv = k4[i];
            Kst[(d + 0) * APAD + r] = kv.x;
            Kst[(d + 1) * APAD + r] = kv.y;
            Kst[(d + 2) * APAD + r] = kv.z;
            Kst[(d + 3) * APAD + r] = kv.w;
            *(float4*)&Vs[r * APAD + d] = v4[i];
        }
        __syncthreads();

        // S = Q K^T (4x4 microtile)
        float s[4][4] = {};
        #pragma unroll 4
        for (int d = 0; d < 64; d++) {
            float4 a = *(const float4*)&Qst[d * APAD + ty * 4];
            float4 b = *(const float4*)&Kst[d * APAD + tx * 4];
            float av[4] = {a.x, a.y, a.z, a.w};
            float bv[4] = {b.x, b.y, b.z, b.w};
            #pragma unroll
            for (int ii = 0; ii < 4; ii++)
                #pragma unroll
                for (int jj = 0; jj < 4; jj++)
                    s[ii][jj] = fmaf(av[ii], bv[jj], s[ii][jj]);
        }

        // + rel-key, scale, tile row max
        const int kb = kt * 64 + tx * 4;
        float tmax[4];
        #pragma unroll
        for (int ii = 0; ii < 4; ii++) tmax[ii] = -1e30f;
        #pragma unroll
        for (int ii = 0; ii < 4; ii++) {
            int qg = qg0 + ii;
            #pragma unroll
            for (int jj = 0; jj < 4; jj++) {
                int diff = kb + jj - qg;
                int dcl = diff < -CLIPV ? 0 : (diff > CLIPV ? 2 * CLIPV : diff + CLIPV);
                float v = (s[ii][jj] + QR[(ty * 4 + ii) * ND + dcl]) * 0.03125f;
                s[ii][jj] = v;
                tmax[ii] = fmaxf(tmax[ii], v);
            }
        }
        #pragma unroll
        for (int ii = 0; ii < 4; ii++) {
            float t = tmax[ii];
            t = fmaxf(t, __shfl_xor_sync(0xffffffffu, t, 1));
            t = fmaxf(t, __shfl_xor_sync(0xffffffffu, t, 2));
            t = fmaxf(t, __shfl_xor_sync(0xffffffffu, t, 4));
            t = fmaxf(t, __shfl_xor_sync(0xffffffffu, t, 8));
            tmax[ii] = t;
        }
        float corr[4];
        #pragma unroll
        for (int ii = 0; ii < 4; ii++) {
            float mn = fmaxf(m[ii], tmax[ii]);
            corr[ii] = __expf(m[ii] - mn);
            m[ii] = mn;
            l[ii] *= corr[ii]; lo[ii] *= corr[ii]; hi[ii] *= corr[ii];
            #pragma unroll
            for (int jj = 0; jj < 4; jj++) O[ii][jj] *= corr[ii];
        }
        // rescale interior rel-weight buffer (16 tx lanes per row)
        #pragma unroll
        for (int ii = 0; ii < 4; ii++) {
            int q = ty * 4 + ii;
            for (int dd = tx; dd < 31; dd += 16) RB[q * 32 + dd] *= corr[ii];
        }
        __syncwarp();

        // exp, classify, stage P
        float p[4][4];
        #pragma unroll
        for (int ii = 0; ii < 4; ii++) {
            int qg = qg0 + ii;
            #pragma unroll
            for (int jj = 0; jj < 4; jj++) {
                float e = __expf(s[ii][jj] - m[ii]);
                l[ii] += e;
                int diff = kb + jj - qg;
                if (diff <= -CLIPV)      lo[ii] += e;
                else if (diff >= CLIPV)  hi[ii] += e;
                else                     RB[(ty * 4 + ii) * 32 + diff + CLIPV - 1] = e;
                p[ii][jj] = e;
            }
        }
        #pragma unroll
        for (int jj = 0; jj < 4; jj++) {
            float4 pv = make_float4(p[0][jj], p[1][jj], p[2][jj], p[3][jj]);
            *(float4*)&Pst[(tx * 4 + jj) * APAD + ty * 4] = pv;
        }
        __syncthreads();

        // O += P V
        #pragma unroll 4
        for (int k = 0; k < 64; k++) {
            float4 a = *(const float4*)&Pst[k * APAD + ty * 4];
            float4 b = *(const float4*)&Vs[k * APAD + tx * 4];
            float av[4] = {a.x, a.y, a.z, a.w};
            float bv[4] = {b.x, b.y, b.z, b.w};
            #pragma unroll
            for (int ii = 0; ii < 4; ii++)
                #pragma unroll
                for (int jj = 0; jj < 4; jj++)
                    O[ii][jj] = fmaf(av[ii], bv[jj], O[ii][jj]);
        }
        __syncthreads();
    }

    // reduce row stats across the 16 tx lanes
    #pragma unroll
    for (int ii = 0; ii < 4; ii++) {
        #pragma unroll
        for (int off = 1; off < 16; off <<= 1) {
            l[ii]  += __shfl_xor_sync(0xffffffffu, l[ii],  off);
            lo[ii] += __shfl_xor_sync(0xffffffffu, lo[ii], off);
            hi[ii] += __shfl_xor_sync(0xffffffffu, hi[ii], off);
        }
    }

    // relative-value contributions
    {
        float4 r0  = *(const float4*)&RV[0 * 64 + tx * 4];
        float4 r32 = *(const float4*)&RV[32 * 64 + tx * 4];
        float r0v[4]  = {r0.x, r0.y, r0.z, r0.w};
        float r32v[4] = {r32.x, r32.y, r32.z, r32.w};
        #pragma unroll
        for (int ii = 0; ii < 4; ii++)
            #pragma unroll
            for (int jj = 0; jj < 4; jj++)
                O[ii][jj] += lo[ii] * r0v[jj] + hi[ii] * r32v[jj];
    }
    for (int dd = 1; dd < 32; dd++) {
        float4 rv = *(const float4*)&RV[dd * 64 + tx * 4];
        float rvv[4] = {rv.x, rv.y, rv.z, rv.w};
        #pragma unroll
        for (int ii = 0; ii < 4; ii++) {
            float w = RB[(ty * 4 + ii) * 32 + dd - 1];
            #pragma unroll
            for (int jj = 0; jj < 4; jj++)
                O[ii][jj] = fmaf(w, rvv[jj], O[ii][jj]);
        }
    }

    const int bb = bh >> 4, h = bh & 15;
    #pragma unroll
    for (int ii = 0; ii < 4; ii++) {
        float inv = 1.0f / l[ii];
        float4 o = make_float4(O[ii][0] * inv, O[ii][1] * inv, O[ii][2] * inv, O[ii][3] * inv);
        *(float4*)&g_ctx[((size_t)(bb * SEQ + qg0 + ii)) * DKEY + h * HDIM + tx * 4] = o;
    }
}

// ---------------------------------------------------------------------------
extern "C" void kernel_launch(void* const* d_in, const int* in_sizes, int n_in,
                              void* d_out, int out_size)
{
    (void)in_sizes; (void)n_in; (void)out_size;
    const float* q    = (const float*)d_in[0];
    const float* k    = (const float*)d_in[1];
    const float* v    = (const float*)d_in[2];
    const float* Wq   = (const float*)d_in[3];
    const float* bq   = (const float*)d_in[4];
    const float* Wk   = (const float*)d_in[5];
    const float* bk   = (const float*)d_in[6];
    const float* Wv   = (const float*)d_in[7];
    const float* bv   = (const float*)d_in[8];
    const float* Wo   = (const float*)d_in[9];
    const float* bo   = (const float*)d_in[10];
    const float* relk = (const float*)d_in[11];
    const float* relv = (const float*)d_in[12];
    float* out = (float*)d_out;

    float *qh, *kh, *vh, *ctx;
    cudaGetSymbolAddress((void**)&qh, g_qh);
    cudaGetSymbolAddress((void**)&kh, g_kh);
    cudaGetSymbolAddress((void**)&vh, g_vh);
    cudaGetSymbolAddress((void**)&ctx, g_ctx);

    cudaFuncSetAttribute(proj_mma, cudaFuncAttributeMaxDynamicSharedMemorySize, PSMEM);
    cudaFuncSetAttribute(attn_kernel, cudaFuncAttributeMaxDynamicSharedMemorySize, A_TOT * 4);

    dim3 gProj(DKEY / 128, MROWS / 128);   // (8, 32)
    proj_mma<<<gProj, 256, PSMEM>>>(q, Wq, bq, qh, 1);
    proj_mma<<<gProj, 256, PSMEM>>>(k, Wk, bk, kh, 1);
    proj_mma<<<gProj, 256, PSMEM>>>(v, Wv, bv, vh, 1);

    dim3 gAttn(SEQ / 64, BH);              // (32, 32)
    qrel_kernel<<<gAttn, 256>>>(relk);
    attn_kernel<<<gAttn, 256, A_TOT * 4>>>(relv);

    proj_mma<<<gProj, 256, PSMEM>>>(ctx, Wo, bo, out, 0);
}

// round 8
// speedup vs baseline: 5.2814x; 1.5116x over previous
#include <cuda_runtime.h>
#include <cstdint>

// ---------------------------------------------------------------------------
// MultiHeadAttention w/ Shaw relative position. B=2, L=2048, E=1024, H=16,
// hd=64, clip=16.  compute_103 path -> mma.sync.m16n8k8 tf32 tensor cores.
//  1) q/k/v projections + ReLU: mma.sync tf32 GEMM -> split-head [BH][L][64]
//  2) qrel[bh][q][d33] = qh . rel_k[d33]
//  3) flash attention: S=QK^T and O=PV on mma.sync tf32; softmax + Shaw-rel
//     bookkeeping scalar via smem round-trip (proven structure).
//  4) out projection + ReLU: mma.sync tf32 GEMM
// ---------------------------------------------------------------------------

#define BATCH  2
#define SEQ    2048
#define EMB    1024
#define NHEADS 16
#define HDIM   64
#define DKEY   1024
#define CLIPV  16
#define ND     33
#define MROWS  (BATCH*SEQ)
#define BH     (BATCH*NHEADS)

__device__ __align__(256) float g_qh[BH*SEQ*HDIM];
__device__ __align__(256) float g_kh[BH*SEQ*HDIM];
__device__ __align__(256) float g_vh[BH*SEQ*HDIM];
__device__ __align__(256) float g_qrel[BH*SEQ*ND];
__device__ __align__(256) float g_ctx[MROWS*DKEY];

__device__ __forceinline__ float tf32r(float x) {
    asm("cvt.rna.tf32.f32 %0, %0;" : "+f"(x));
    return x;
}
__device__ __forceinline__ void mma_tf32(
    float& d0, float& d1, float& d2, float& d3,
    uint32_t a0, uint32_t a1, uint32_t a2, uint32_t a3,
    uint32_t b0, uint32_t b1)
{
    asm volatile(
        "mma.sync.aligned.m16n8k8.row.col.f32.tf32.tf32.f32 "
        "{%0,%1,%2,%3}, {%4,%5,%6,%7}, {%8,%9}, {%0,%1,%2,%3};"
        : "+f"(d0), "+f"(d1), "+f"(d2), "+f"(d3)
        : "r"(a0), "r"(a1), "r"(a2), "r"(a3), "r"(b0), "r"(b1));
}

// ---------------------------------------------------------------------------
// mma.sync tf32 GEMM projections (validated R7). CTA 128x128, BK=16.
// ---------------------------------------------------------------------------
#define PM_PAD 20
#define PM_BUF (128 * PM_PAD)
#define PSMEM  (4 * PM_BUF * 4)

__global__ void __launch_bounds__(256) proj_mma(
    const float* __restrict__ X, const float* __restrict__ W,
    const float* __restrict__ bias, float* __restrict__ out, int split)
{
    extern __shared__ float smf[];
    float* As = smf;
    float* Bs = smf + 2 * PM_BUF;

    const int tid = threadIdx.x;
    const int lane = tid & 31, wid = tid >> 5;
    const int wm = wid & 3, wn = wid >> 2;
    const int lr = lane >> 2, lq = lane & 3;
    const int m0 = blockIdx.y * 128, n0 = blockIdx.x * 128;

    const float4* X4 = (const float4*)X;
    const float4* W4 = (const float4*)W;

    const int r0 = tid >> 2, c0 = tid & 3;
    const int r1 = (tid + 256) >> 2, c1 = tid & 3;

    float c[2][8][4];
    #pragma unroll
    for (int i = 0; i < 2; i++)
        #pragma unroll
        for (int j = 0; j < 8; j++)
            #pragma unroll
            for (int t = 0; t < 4; t++) c[i][j][t] = 0.f;

    {
        float4 xa0 = X4[(size_t)(m0 + r0) * 256 + c0];
        float4 xa1 = X4[(size_t)(m0 + r1) * 256 + c1];
        float4 wb0 = W4[(size_t)(n0 + r0) * 256 + c0];
        float4 wb1 = W4[(size_t)(n0 + r1) * 256 + c1];
        float* a = As; float* b = Bs;
        a[r0*PM_PAD + c0*4+0] = tf32r(xa0.x); a[r0*PM_PAD + c0*4+1] = tf32r(xa0.y);
        a[r0*PM_PAD + c0*4+2] = tf32r(xa0.z); a[r0*PM_PAD + c0*4+3] = tf32r(xa0.w);
        a[r1*PM_PAD + c1*4+0] = tf32r(xa1.x); a[r1*PM_PAD + c1*4+1] = tf32r(xa1.y);
        a[r1*PM_PAD + c1*4+2] = tf32r(xa1.z); a[r1*PM_PAD + c1*4+3] = tf32r(xa1.w);
        b[r0*PM_PAD + c0*4+0] = tf32r(wb0.x); b[r0*PM_PAD + c0*4+1] = tf32r(wb0.y);
        b[r0*PM_PAD + c0*4+2] = tf32r(wb0.z); b[r0*PM_PAD + c0*4+3] = tf32r(wb0.w);
        b[r1*PM_PAD + c1*4+0] = tf32r(wb1.x); b[r1*PM_PAD + c1*4+1] = tf32r(wb1.y);
        b[r1*PM_PAD + c1*4+2] = tf32r(wb1.z); b[r1*PM_PAD + c1*4+3] = tf32r(wb1.w);
    }
    __syncthreads();

    for (int kc = 0; kc < 64; kc++) {
        const int buf = kc & 1;
        float4 xa0, xa1, wb0, wb1;
        if (kc + 1 < 64) {
            const int kb = (kc + 1) * 4;
            xa0 = X4[(size_t)(m0 + r0) * 256 + kb + c0];
            xa1 = X4[(size_t)(m0 + r1) * 256 + kb + c1];
            wb0 = W4[(size_t)(n0 + r0) * 256 + kb + c0];
            wb1 = W4[(size_t)(n0 + r1) * 256 + kb + c1];
        }

        const float* a = As + buf * PM_BUF;
        const float* b = Bs + buf * PM_BUF;
        #pragma unroll
        for (int ks = 0; ks < 2; ks++) {
            const int k0 = ks * 8 + lq;
            uint32_t af[2][4];
            #pragma unroll
            for (int mt = 0; mt < 2; mt++) {
                const int row = wm * 32 + mt * 16 + lr;
                af[mt][0] = __float_as_uint(a[row * PM_PAD + k0]);
                af[mt][1] = __float_as_uint(a[(row + 8) * PM_PAD + k0]);
                af[mt][2] = __float_as_uint(a[row * PM_PAD + k0 + 4]);
                af[mt][3] = __float_as_uint(a[(row + 8) * PM_PAD + k0 + 4]);
            }
            #pragma unroll
            for (int nt = 0; nt < 8; nt++) {
                const int col = wn * 64 + nt * 8 + lr;
                uint32_t b0 = __float_as_uint(b[col * PM_PAD + k0]);
                uint32_t b1 = __float_as_uint(b[col * PM_PAD + k0 + 4]);
                #pragma unroll
                for (int mt = 0; mt < 2; mt++)
                    mma_tf32(c[mt][nt][0], c[mt][nt][1], c[mt][nt][2], c[mt][nt][3],
                             af[mt][0], af[mt][1], af[mt][2], af[mt][3], b0, b1);
            }
        }

        if (kc + 1 < 64) {
            float* an = As + (buf ^ 1) * PM_BUF;
            float* bn = Bs + (buf ^ 1) * PM_BUF;
            an[r0*PM_PAD + c0*4+0] = tf32r(xa0.x); an[r0*PM_PAD + c0*4+1] = tf32r(xa0.y);
            an[r0*PM_PAD + c0*4+2] = tf32r(xa0.z); an[r0*PM_PAD + c0*4+3] = tf32r(xa0.w);
            an[r1*PM_PAD + c1*4+0] = tf32r(xa1.x); an[r1*PM_PAD + c1*4+1] = tf32r(xa1.y);
            an[r1*PM_PAD + c1*4+2] = tf32r(xa1.z); an[r1*PM_PAD + c1*4+3] = tf32r(xa1.w);
            bn[r0*PM_PAD + c0*4+0] = tf32r(wb0.x); bn[r0*PM_PAD + c0*4+1] = tf32r(wb0.y);
            bn[r0*PM_PAD + c0*4+2] = tf32r(wb0.z); bn[r0*PM_PAD + c0*4+3] = tf32r(wb0.w);
            bn[r1*PM_PAD + c1*4+0] = tf32r(wb1.x); bn[r1*PM_PAD + c1*4+1] = tf32r(wb1.y);
            bn[r1*PM_PAD + c1*4+2] = tf32r(wb1.z); bn[r1*PM_PAD + c1*4+3] = tf32r(wb1.w);
        }
        __syncthreads();
    }

    #pragma unroll
    for (int mt = 0; mt < 2; mt++) {
        #pragma unroll
        for (int nt = 0; nt < 8; nt++) {
            const int row = m0 + wm * 32 + mt * 16 + lr;
            const int col = n0 + wn * 64 + nt * 8 + 2 * lq;
            const float bia0 = bias[col], bia1 = bias[col + 1];
            #pragma unroll
            for (int half = 0; half < 2; half++) {
                const int m = row + half * 8;
                float v0 = fmaxf(c[mt][nt][half * 2 + 0] + bia0, 0.f);
                float v1 = fmaxf(c[mt][nt][half * 2 + 1] + bia1, 0.f);
                if (split) {
                    const int bb = m >> 11, ll = m & (SEQ - 1);
                    const int h = col >> 6, d = col & 63;
                    out[(((size_t)(bb * NHEADS + h)) * SEQ + ll) * HDIM + d]     = v0;
                    out[(((size_t)(bb * NHEADS + h)) * SEQ + ll) * HDIM + d + 1] = v1;
                } else {
                    float2 v = make_float2(v0, v1);
                    *(float2*)&out[(size_t)m * DKEY + col] = v;
                }
            }
        }
    }
}

// ---------------------------------------------------------------------------
// qrel
// ---------------------------------------------------------------------------
__global__ void __launch_bounds__(256) qrel_kernel(const float* __restrict__ rel_k)
{
    __shared__ float Qs[64 * 64];
    __shared__ float Rk[ND * 65];
    const int bh = blockIdx.y, q0 = blockIdx.x * 64;

    const float* qb = g_qh + ((size_t)bh * SEQ + q0) * HDIM;
    for (int i = threadIdx.x; i < 64 * 64; i += 256) Qs[i] = qb[i];
    for (int i = threadIdx.x; i < ND * 64; i += 256) {
        int d = i >> 6, cc = i & 63;
        Rk[d * 65 + cc] = rel_k[i];
    }
    __syncthreads();

    for (int i = threadIdx.x; i < 64 * ND; i += 256) {
        int q = i / ND, d = i - q * ND;
        float s = 0.f;
        #pragma unroll 8
        for (int cc = 0; cc < 64; cc++) s = fmaf(Qs[q * 64 + cc], Rk[d * 65 + cc], s);
        g_qrel[((size_t)bh * SEQ + q0 + q) * ND + d] = s;
    }
}

// ---------------------------------------------------------------------------
// Flash attention on mma.sync tf32.
// CTA: 64 q-rows x 64 k-tile, 256 thr = 8 warps (4 rowgroups x 2 col-halves).
// Pads: Q/K/S stride 68 (frag residues 4g+t, conflict-free),
//       V stride 72 (frag residues 8t+g, conflict-free).
// ---------------------------------------------------------------------------
#define KPAD 68
#define VPAD 72
#define AS_Q  0
#define AS_K  4352
#define AS_V  8704
#define AS_P  13312
#define AS_QR 17664
#define AS_RB 19776
#define AS_RV 21824
#define AS_CR 23936
#define AS_TOT 24000        // floats -> 96000 bytes

__global__ void __launch_bounds__(256, 2) attn_mma(const float* __restrict__ rel_v)
{
    extern __shared__ float smf[];
    float* Qs = smf + AS_Q;
    float* Ks = smf + AS_K;
    float* Vs = smf + AS_V;
    float* Ps = smf + AS_P;
    float* QR = smf + AS_QR;
    float* RB = smf + AS_RB;
    float* RV = smf + AS_RV;
    float* CR = smf + AS_CR;

    const int tid = threadIdx.x;
    const int lane = tid & 31, wid = tid >> 5;
    const int g = lane >> 2, t = lane & 3;
    const int rg = wid >> 1;          // row group (16 rows)
    const int cg = wid & 1;           // column half
    const int bh = blockIdx.y, q0 = blockIdx.x * 64;
    const int sq = tid >> 2;          // softmax row
    const int seg = tid & 3;          // 16-col segment

    // ---- prologue staging
    const float4* q4 = (const float4*)(g_qh + ((size_t)bh * SEQ + q0) * HDIM);
    for (int i = tid; i < 1024; i += 256) {
        int r = i >> 4, cc = (i & 15) << 2;
        float4 v = q4[i];
        Qs[r*KPAD + cc+0] = tf32r(v.x);
        Qs[r*KPAD + cc+1] = tf32r(v.y);
        Qs[r*KPAD + cc+2] = tf32r(v.z);
        Qs[r*KPAD + cc+3] = tf32r(v.w);
    }
    const float* qrb = g_qrel + ((size_t)bh * SEQ + q0) * ND;
    for (int i = tid; i < 64 * ND; i += 256) QR[i] = qrb[i];
    const float4* rv4 = (const float4*)rel_v;
    for (int i = tid; i < (ND * 64) / 4; i += 256) ((float4*)RV)[i] = rv4[i];
    for (int i = tid; i < 64 * 32; i += 256) RB[i] = 0.f;
    __syncthreads();

    // ---- preload Q fragments (warp rows rg*16 + {g, g+8})
    uint32_t qa[8][4];
    {
        const int rb = rg * 16;
        #pragma unroll
        for (int ks = 0; ks < 8; ks++) {
            qa[ks][0] = __float_as_uint(Qs[(rb+g  )*KPAD + ks*8 + t    ]);
            qa[ks][1] = __float_as_uint(Qs[(rb+g+8)*KPAD + ks*8 + t    ]);
            qa[ks][2] = __float_as_uint(Qs[(rb+g  )*KPAD + ks*8 + t + 4]);
            qa[ks][3] = __float_as_uint(Qs[(rb+g+8)*KPAD + ks*8 + t + 4]);
        }
    }

    float o[4][4] = {};                       // O frags: [d-tile][c]
    float mrow = -1e30f, lrow = 0.f, slo = 0.f, shi = 0.f;

    for (int kt = 0; kt < SEQ / 64; kt++) {
        // ---- stage K, V (direct copy, tf32-rounded)
        const float4* k4 = (const float4*)(g_kh + ((size_t)bh * SEQ + kt*64) * HDIM);
        const float4* v4 = (const float4*)(g_vh + ((size_t)bh * SEQ + kt*64) * HDIM);
        for (int i = tid; i < 1024; i += 256) {
            int r = i >> 4, cc = (i & 15) << 2;
            float4 kv = k4[i];
            Ks[r*KPAD + cc+0] = tf32r(kv.x);
            Ks[r*KPAD + cc+1] = tf32r(kv.y);
            Ks[r*KPAD + cc+2] = tf32r(kv.z);
            Ks[r*KPAD + cc+3] = tf32r(kv.w);
            float4 vv = v4[i];
            Vs[r*VPAD + cc+0] = tf32r(vv.x);
            Vs[r*VPAD + cc+1] = tf32r(vv.y);
            Vs[r*VPAD + cc+2] = tf32r(vv.z);
            Vs[r*VPAD + cc+3] = tf32r(vv.w);
        }
        __syncthreads();

        // ---- S = Q K^T  (warp: 16 rows x 32 cols)
        float s[4][4] = {};
        #pragma unroll
        for (int ks = 0; ks < 8; ks++) {
            #pragma unroll
            for (int nt = 0; nt < 4; nt++) {
                const int col = cg*32 + nt*8 + g;
                uint32_t b0 = __float_as_uint(Ks[col*KPAD + ks*8 + t    ]);
                uint32_t b1 = __float_as_uint(Ks[col*KPAD + ks*8 + t + 4]);
                mma_tf32(s[nt][0], s[nt][1], s[nt][2], s[nt][3],
                         qa[ks][0], qa[ks][1], qa[ks][2], qa[ks][3], b0, b1);
            }
        }
        // store S frags
        {
            const int r0 = rg*16 + g;
            #pragma unroll
            for (int nt = 0; nt < 4; nt++) {
                const int col = cg*32 + nt*8 + 2*t;
                *(float2*)&Ps[ r0     *KPAD + col] = make_float2(s[nt][0], s[nt][1]);
                *(float2*)&Ps[(r0 + 8)*KPAD + col] = make_float2(s[nt][2], s[nt][3]);
            }
        }
        __syncthreads();

        // ---- softmax + Shaw-rel bookkeeping (thread = row sq, 16 cols)
        {
            const int kb = kt*64 + seg*16;
            const int qg = q0 + sq;
            float sv[16];
            float tmax = -1e30f;
            #pragma unroll
            for (int j = 0; j < 16; j++) {
                int diff = kb + j - qg;
                int dcl = diff < -CLIPV ? 0 : (diff > CLIPV ? 2*CLIPV : diff + CLIPV);
                float v = (Ps[sq*KPAD + seg*16 + j] + QR[sq*ND + dcl]) * 0.03125f;
                sv[j] = v;
                tmax = fmaxf(tmax, v);
            }
            tmax = fmaxf(tmax, __shfl_xor_sync(0xffffffffu, tmax, 1));
            tmax = fmaxf(tmax, __shfl_xor_sync(0xffffffffu, tmax, 2));
            float mn = fmaxf(mrow, tmax);
            float corr = __expf(mrow - mn);
            mrow = mn;
            lrow *= corr; slo *= corr; shi *= corr;
            for (int dd = seg; dd < 31; dd += 4) RB[sq*32 + dd] *= corr;
            if (seg == 0) CR[sq] = corr;
            __syncwarp();
            #pragma unroll
            for (int j = 0; j < 16; j++) {
                float e = __expf(sv[j] - mn);
                lrow += e;
                int diff = kb + j - qg;
                if (diff <= -CLIPV)      slo += e;
                else if (diff >= CLIPV)  shi += e;
                else                     RB[sq*32 + diff + CLIPV - 1] = e;
                Ps[sq*KPAD + seg*16 + j] = e;
            }
        }
        __syncthreads();

        // ---- O = O*corr + P V   (warp: 16 rows x 32 d-dims)
        {
            const float cA = CR[rg*16 + g], cB = CR[rg*16 + g + 8];
            #pragma unroll
            for (int nt = 0; nt < 4; nt++) {
                o[nt][0] *= cA; o[nt][1] *= cA;
                o[nt][2] *= cB; o[nt][3] *= cB;
            }
            const int r0 = rg * 16;
            #pragma unroll
            for (int ks = 0; ks < 8; ks++) {
                uint32_t pa0 = __float_as_uint(Ps[(r0+g  )*KPAD + ks*8 + t    ]);
                uint32_t pa1 = __float_as_uint(Ps[(r0+g+8)*KPAD + ks*8 + t    ]);
                uint32_t pa2 = __float_as_uint(Ps[(r0+g  )*KPAD + ks*8 + t + 4]);
                uint32_t pa3 = __float_as_uint(Ps[(r0+g+8)*KPAD + ks*8 + t + 4]);
                #pragma unroll
                for (int nt = 0; nt < 4; nt++) {
                    const int d = cg*32 + nt*8 + g;
                    uint32_t b0 = __float_as_uint(Vs[(ks*8 + t    )*VPAD + d]);
                    uint32_t b1 = __float_as_uint(Vs[(ks*8 + t + 4)*VPAD + d]);
                    mma_tf32(o[nt][0], o[nt][1], o[nt][2], o[nt][3],
                             pa0, pa1, pa2, pa3, b0, b1);
                }
            }
        }
        __syncthreads();
    }

    // ---- write O frags to smem for thread-layout epilogue
    {
        const int r0 = rg*16 + g;
        #pragma unroll
        for (int nt = 0; nt < 4; nt++) {
            const int col = cg*32 + nt*8 + 2*t;
            *(float2*)&Ps[ r0     *KPAD + col] = make_float2(o[nt][0], o[nt][1]);
            *(float2*)&Ps[(r0 + 8)*KPAD + col] = make_float2(o[nt][2], o[nt][3]);
        }
    }
    __syncthreads();

    // ---- final row-stat reduce (quad)
    lrow += __shfl_xor_sync(0xffffffffu, lrow, 1);
    lrow += __shfl_xor_sync(0xffffffffu, lrow, 2);
    slo  += __shfl_xor_sync(0xffffffffu, slo, 1);
    slo  += __shfl_xor_sync(0xffffffffu, slo, 2);
    shi  += __shfl_xor_sync(0xffffffffu, shi, 1);
    shi  += __shfl_xor_sync(0xffffffffu, shi, 2);

    // ---- epilogue: rel-value contributions + normalize + store
    {
        float O[16];
        #pragma unroll
        for (int j = 0; j < 16; j++) O[j] = Ps[sq*KPAD + seg*16 + j];
        const int cb = seg * 16;
        #pragma unroll
        for (int j = 0; j < 16; j++)
            O[j] += slo * RV[0*64 + cb + j] + shi * RV[32*64 + cb + j];
        for (int dd = 1; dd < 32; dd++) {
            float w = RB[sq*32 + dd - 1];
            #pragma unroll
            for (int j = 0; j < 16; j++)
                O[j] = fmaf(w, RV[dd*64 + cb + j], O[j]);
        }
        const float inv = 1.0f / lrow;
        const int bb = bh >> 4, h = bh & 15;
        float* dst = &g_ctx[((size_t)(bb * SEQ + q0 + sq)) * DKEY + h * HDIM + cb];
        #pragma unroll
        for (int u = 0; u < 4; u++) {
            float4 v = make_float4(O[u*4+0]*inv, O[u*4+1]*inv, O[u*4+2]*inv, O[u*4+3]*inv);
            *(float4*)&dst[u*4] = v;
        }
    }
}

// ---------------------------------------------------------------------------
extern "C" void kernel_launch(void* const* d_in, const int* in_sizes, int n_in,
                              void* d_out, int out_size)
{
    (void)in_sizes; (void)n_in; (void)out_size;
    const float* q    = (const float*)d_in[0];
    const float* k    = (const float*)d_in[1];
    const float* v    = (const float*)d_in[2];
    const float* Wq   = (const float*)d_in[3];
    const float* bq   = (const float*)d_in[4];
    const float* Wk   = (const float*)d_in[5];
    const float* bk   = (const float*)d_in[6];
    const float* Wv   = (const float*)d_in[7];
    const float* bv   = (const float*)d_in[8];
    const float* Wo   = (const float*)d_in[9];
    const float* bo   = (const float*)d_in[10];
    const float* relk = (const float*)d_in[11];
    const float* relv = (const float*)d_in[12];
    float* out = (float*)d_out;

    float *qh, *kh, *vh, *ctx;
    cudaGetSymbolAddress((void**)&qh, g_qh);
    cudaGetSymbolAddress((void**)&kh, g_kh);
    cudaGetSymbolAddress((void**)&vh, g_vh);
    cudaGetSymbolAddress((void**)&ctx, g_ctx);

    cudaFuncSetAttribute(proj_mma, cudaFuncAttributeMaxDynamicSharedMemorySize, PSMEM);
    cudaFuncSetAttribute(attn_mma, cudaFuncAttributeMaxDynamicSharedMemorySize, AS_TOT * 4);

    dim3 gProj(DKEY / 128, MROWS / 128);   // (8, 32)
    proj_mma<<<gProj, 256, PSMEM>>>(q, Wq, bq, qh, 1);
    proj_mma<<<gProj, 256, PSMEM>>>(k, Wk, bk, kh, 1);
    proj_mma<<<gProj, 256, PSMEM>>>(v, Wv, bv, vh, 1);

    dim3 gAttn(SEQ / 64, BH);              // (32, 32)
    qrel_kernel<<<gAttn, 256>>>(relk);
    attn_mma<<<gAttn, 256, AS_TOT * 4>>>(relv);

    proj_mma<<<gProj, 256, PSMEM>>>(ctx, Wo, bo, out, 0);
}